// round 15
// baseline (speedup 1.0000x reference)
#include <cuda_runtime.h>
#include <cuda_bf16.h>
#include <cuda.h>
#include <cstdint>

// ---------------------------------------------------------------------------
// QLinear, round 15 = round 14 (best, 468us) + ONE change:
//   tc path skips the g_qx s8 store in k_quant (-32MB DRAM traffic);
//   k_cand computes candidate corrections from bf16(qx') x s8(qe) via FFMA
//   (products are exact integers in fp32).
// Everything else byte-identical to round 14.
// ---------------------------------------------------------------------------

#if defined(__CUDA_ARCH__) && (__CUDA_ARCH__ == 1030) && \
    (defined(__CUDA_ARCH_FEAT_SM103_ALL) || \
     (defined(__CUDA_ARCH_SPECIFIC__) && (__CUDA_ARCH_SPECIFIC__ == 1030)) || \
     (defined(__CUDA_ARCH_FAMILY_SPECIFIC__) && (__CUDA_ARCH_FAMILY_SPECIFIC__ == 1030)))
#define HAVE_TC 1
#else
#define HAVE_TC 0
#endif

#define MAXM 8192
#define MAXN 4096
#define MAXK 4096

__device__ signed char    g_qx [(size_t)MAXM * MAXK];   // fallback path only
__device__ signed char    g_qw [(size_t)MAXN * MAXK];   // fallback only
__device__ signed char    g_qe [(size_t)MAXN * MAXK];
__device__ __nv_bfloat16  g_qxh[(size_t)MAXM * MAXK];
__device__ __nv_bfloat16  g_qwh[(size_t)MAXN * MAXK];
__device__ int   g_rsx [MAXM];
__device__ int   g_rsw [MAXN];
__device__ int   g_rsqe[MAXN];
__device__ unsigned long long g_sq[2];
__device__ unsigned g_keys[8];  // xmin,xmax,wmin,wmax, pre_min,pre_max, act_min,act_max
__device__ float g_xs, g_xzp, g_wsc, g_wzp, g_es, g_as, g_azp;
__device__ int   g_xzpi, g_wzpi;

__device__ __forceinline__ unsigned fkey(float v) {
    unsigned u = __float_as_uint(v);
    return (u & 0x80000000u) ? ~u : (u | 0x80000000u);
}
__device__ __forceinline__ float fdec(unsigned k) {
    unsigned u = (k & 0x80000000u) ? (k & 0x7FFFFFFFu) : ~k;
    return __uint_as_float(u);
}

// ---- prologue kernels -------------------------------------------------------
__global__ void k_init() {
    if (threadIdx.x == 0) {
        g_keys[0] = 0xFFFFFFFFu; g_keys[1] = 0u;
        g_keys[2] = 0xFFFFFFFFu; g_keys[3] = 0u;
        g_keys[4] = 0xFFFFFFFFu; g_keys[5] = 0u;
        g_keys[6] = 0xFFFFFFFFu; g_keys[7] = 0u;
        g_sq[0] = 0ull; g_sq[1] = 0ull;
    }
}

// Fused min/max over x (blocks [0,gx)) and w (blocks [gx,grid)).
__global__ void k_minmax2(const float* __restrict__ x, long long n4x,
                          const float* __restrict__ w, long long n4w, int gx) {
    const float4* p4;
    long long n4; int imin, imax, nb, bid;
    if (blockIdx.x < (unsigned)gx) {
        p4 = (const float4*)x; n4 = n4x; imin = 0; imax = 1;
        nb = gx; bid = blockIdx.x;
    } else {
        p4 = (const float4*)w; n4 = n4w; imin = 2; imax = 3;
        nb = gridDim.x - gx; bid = blockIdx.x - gx;
    }
    float lmin = __int_as_float(0x7f800000);
    float lmax = -lmin;
    for (long long i = bid * (long long)blockDim.x + threadIdx.x; i < n4;
         i += (long long)nb * blockDim.x) {
        float4 v = p4[i];
        lmin = fminf(lmin, fminf(fminf(v.x, v.y), fminf(v.z, v.w)));
        lmax = fmaxf(lmax, fmaxf(fmaxf(v.x, v.y), fmaxf(v.z, v.w)));
    }
    #pragma unroll
    for (int o = 16; o > 0; o >>= 1) {
        lmin = fminf(lmin, __shfl_xor_sync(0xffffffffu, lmin, o));
        lmax = fmaxf(lmax, __shfl_xor_sync(0xffffffffu, lmax, o));
    }
    __shared__ float smin[8], smax[8];
    int w8 = threadIdx.x >> 5;
    if ((threadIdx.x & 31) == 0) { smin[w8] = lmin; smax[w8] = lmax; }
    __syncthreads();
    if (threadIdx.x == 0) {
        int nw = (int)(blockDim.x >> 5);
        for (int i = 1; i < nw; i++) { lmin = fminf(lmin, smin[i]); lmax = fmaxf(lmax, smax[i]); }
        atomicMin(&g_keys[imin], fkey(lmin));
        atomicMax(&g_keys[imax], fkey(lmax));
    }
}

__global__ void k_scales1() {
    float xmin = fdec(g_keys[0]), xmax = fdec(g_keys[1]);
    float wmin = fdec(g_keys[2]), wmax = fdec(g_keys[3]);
    float xs = (xmax - xmin) / 255.0f;
    float xzp = rintf(0.0f - xmin / xs);
    g_xs = xs; g_xzp = xzp; g_xzpi = (int)xzp - 128;
    float ws = (wmax - wmin) / 255.0f;
    float wzp = rintf(-128.0f - wmin / ws);
    g_wsc = ws; g_wzp = wzp; g_wzpi = (int)wzp;
    g_es = ws / 127.0f;
}

// Fused quantization: blocks [0,M) quantize x rows; blocks [M,M+N) quantize w rows.
__global__ void k_quant(const float* __restrict__ x, const float* __restrict__ w,
                        int M, int K) {
    __shared__ int ss[8], se[8];
    __shared__ long long sqs[8];
    if ((int)blockIdx.x < M) {
        int row = blockIdx.x;
        const float* xr = x + (size_t)row * K;
        __nv_bfloat16* hr = g_qxh + (size_t)row * K;
#if !HAVE_TC
        signed char* qr = g_qx + (size_t)row * K;
#endif
        float xs = g_xs, xzp = g_xzp;
        int sum = 0; long long sq = 0;
        for (int k = threadIdx.x * 4; k < K; k += blockDim.x * 4) {
            float4 v = *(const float4*)(xr + k);
            int q0 = (int)fminf(255.f, fmaxf(0.f, rintf(v.x / xs + xzp))) - 128;
            int q1 = (int)fminf(255.f, fmaxf(0.f, rintf(v.y / xs + xzp))) - 128;
            int q2 = (int)fminf(255.f, fmaxf(0.f, rintf(v.z / xs + xzp))) - 128;
            int q3 = (int)fminf(255.f, fmaxf(0.f, rintf(v.w / xs + xzp))) - 128;
            sum += q0 + q1 + q2 + q3;
            sq  += q0 * q0 + q1 * q1 + q2 * q2 + q3 * q3;
#if HAVE_TC
            *(__nv_bfloat162*)(hr + k)     = __floats2bfloat162_rn((float)q0, (float)q1);
            *(__nv_bfloat162*)(hr + k + 2) = __floats2bfloat162_rn((float)q2, (float)q3);
#else
            unsigned pk = (unsigned)(q0 & 0xFF) | ((unsigned)(q1 & 0xFF) << 8) |
                          ((unsigned)(q2 & 0xFF) << 16) | ((unsigned)(q3 & 0xFF) << 24);
            *(unsigned*)(qr + k) = pk;
#endif
        }
        #pragma unroll
        for (int o = 16; o > 0; o >>= 1) {
            sum += __shfl_xor_sync(0xffffffffu, sum, o);
            sq  += __shfl_xor_sync(0xffffffffu, sq, o);
        }
        if ((threadIdx.x & 31) == 0) { ss[threadIdx.x >> 5] = sum; sqs[threadIdx.x >> 5] = sq; }
        __syncthreads();
        if (threadIdx.x == 0) {
            int t = 0; long long tq = 0; int nw = (int)(blockDim.x >> 5);
            for (int i = 0; i < nw; i++) { t += ss[i]; tq += sqs[i]; }
            g_rsx[row] = t;
            atomicAdd(&g_sq[0], (unsigned long long)tq);
        }
    } else {
        int row = blockIdx.x - M;
        const float* wr = w + (size_t)row * K;
        signed char* er = g_qe + (size_t)row * K;
        __nv_bfloat16* qh = g_qwh + (size_t)row * K;
#if !HAVE_TC
        signed char* qr = g_qw + (size_t)row * K;
#endif
        float ws = g_wsc, wzp = g_wzp, es = g_es;
        int isum = 0, esum = 0; long long esq = 0;
        for (int k = threadIdx.x * 4; k < K; k += blockDim.x * 4) {
            float4 v = *(const float4*)(wr + k);
            float qf[4];
            qf[0] = fminf(127.f, fmaxf(-128.f, rintf(v.x / ws + wzp)));
            qf[1] = fminf(127.f, fmaxf(-128.f, rintf(v.y / ws + wzp)));
            qf[2] = fminf(127.f, fmaxf(-128.f, rintf(v.z / ws + wzp)));
            qf[3] = fminf(127.f, fmaxf(-128.f, rintf(v.w / ws + wzp)));
            float ev[4];
            ev[0] = v.x - (qf[0] - wzp) * ws;
            ev[1] = v.y - (qf[1] - wzp) * ws;
            ev[2] = v.z - (qf[2] - wzp) * ws;
            ev[3] = v.w - (qf[3] - wzp) * ws;
            int q[4], qe[4];
            #pragma unroll
            for (int j = 0; j < 4; j++) {
                q[j]  = (int)qf[j];
                qe[j] = (int)fminf(127.f, fmaxf(-127.f, rintf(ev[j] / es)));
                isum += q[j]; esum += qe[j]; esq += qe[j] * qe[j];
            }
            unsigned pe = (unsigned)(qe[0] & 0xFF) | ((unsigned)(qe[1] & 0xFF) << 8) |
                          ((unsigned)(qe[2] & 0xFF) << 16) | ((unsigned)(qe[3] & 0xFF) << 24);
            *(unsigned*)(er + k) = pe;
#if HAVE_TC
            *(__nv_bfloat162*)(qh + k)     = __floats2bfloat162_rn((float)q[0], (float)q[1]);
            *(__nv_bfloat162*)(qh + k + 2) = __floats2bfloat162_rn((float)q[2], (float)q[3]);
#else
            unsigned pq = (unsigned)(q[0] & 0xFF) | ((unsigned)(q[1] & 0xFF) << 8) |
                          ((unsigned)(q[2] & 0xFF) << 16) | ((unsigned)(q[3] & 0xFF) << 24);
            *(unsigned*)(qr + k) = pq;
#endif
        }
        #pragma unroll
        for (int o = 16; o > 0; o >>= 1) {
            isum += __shfl_xor_sync(0xffffffffu, isum, o);
            esum += __shfl_xor_sync(0xffffffffu, esum, o);
            esq  += __shfl_xor_sync(0xffffffffu, esq, o);
        }
        if ((threadIdx.x & 31) == 0) {
            ss[threadIdx.x >> 5] = isum; se[threadIdx.x >> 5] = esum;
            sqs[threadIdx.x >> 5] = esq;
        }
        __syncthreads();
        if (threadIdx.x == 0) {
            int ti = 0, te = 0; long long tq = 0; int nw = (int)(blockDim.x >> 5);
            for (int i = 0; i < nw; i++) { ti += ss[i]; te += se[i]; tq += sqs[i]; }
            g_rsw[row] = ti; g_rsqe[row] = te;
            atomicAdd(&g_sq[1], (unsigned long long)tq);
        }
    }
}

// ===========================================================================
// Engine A: tcgen05 cg1, tile 256Mx256N, TMA-fed, 3 stages x 64KB,
// cluster(2,1,1) A-multicast. Proven round-10/11/14 structure, unchanged.
// ===========================================================================
#define STAGES      3
#define STAGE_BYTES 65536
#define TILE_BASE   1024
#define SMEM_TC     (TILE_BASE + STAGES * STAGE_BYTES)

#if HAVE_TC
#define MBAR_INIT(addr, cnt) \
    asm volatile("mbarrier.init.shared.b64 [%0], %1;" :: "r"(addr), "r"(cnt) : "memory")

#define MBAR_WAIT(addr, ph) do {                                              \
    unsigned _m = (addr), _p = (ph), _d;                                      \
    asm volatile("{\n\t.reg .pred p;\n\t"                                     \
        "mbarrier.try_wait.parity.acquire.cta.shared::cta.b64 p, [%1], %2;\n\t" \
        "selp.b32 %0, 1, 0, p;\n\t}" : "=r"(_d) : "r"(_m), "r"(_p) : "memory"); \
    if (!_d) {                                                                \
        asm volatile("{\n\t.reg .pred P1;\n\t"                                \
            "W%=:\n\t"                                                        \
            "mbarrier.try_wait.parity.acquire.cta.shared::cta.b64 P1, [%0], %1, 0x989680;\n\t" \
            "@P1 bra.uni D%=;\n\t"                                            \
            "bra.uni W%=;\n\t"                                                \
            "D%=:\n\t}" :: "r"(_m), "r"(_p) : "memory");                      \
    }                                                                         \
} while (0)

#define MBAR_EXPECT_TX(addr, bytes) \
    asm volatile("mbarrier.arrive.expect_tx.shared.b64 _, [%0], %1;" \
                 :: "r"(addr), "r"(bytes) : "memory")

#define TC_COMMIT(addr) \
    asm volatile("tcgen05.commit.cta_group::1.mbarrier::arrive::one.shared::cluster.b64 [%0];" \
                 :: "r"(addr) : "memory")

#define TC_COMMIT_MC(addr, mask) \
    asm volatile("tcgen05.commit.cta_group::1.mbarrier::arrive::one.shared::cluster.multicast::cluster.b64 [%0], %1;" \
                 :: "r"(addr), "h"((unsigned short)(mask)) : "memory")

#define TMA_2D(smem, map, cx, cy, mbar) \
    asm volatile("cp.async.bulk.tensor.2d.shared::cta.global.tile.mbarrier::complete_tx::bytes " \
                 "[%0], [%1, {%2, %3}], [%4];" \
                 :: "r"(smem), "l"(map), "r"(cx), "r"(cy), "r"(mbar) : "memory")

#define TMA_2D_MC(smem, map, cx, cy, mbar, mask) \
    asm volatile("cp.async.bulk.tensor.2d.shared::cluster.global.tile.mbarrier::complete_tx::bytes.multicast::cluster " \
                 "[%0], [%1, {%2, %3}], [%4], %5;" \
                 :: "r"(smem), "l"(map), "r"(cx), "r"(cy), "r"(mbar), \
                    "h"((unsigned short)(mask)) : "memory")

#define CLUSTER_SYNC() do { \
    asm volatile("barrier.cluster.arrive.aligned;" ::: "memory"); \
    asm volatile("barrier.cluster.wait.aligned;" ::: "memory"); \
} while (0)

#define LDTM_X32(r, a) \
    asm volatile("tcgen05.ld.sync.aligned.32x32b.x32.b32 " \
        "{%0,%1,%2,%3,%4,%5,%6,%7,%8,%9,%10,%11,%12,%13,%14,%15," \
        "%16,%17,%18,%19,%20,%21,%22,%23,%24,%25,%26,%27,%28,%29,%30,%31}, [%32];" \
        : "=r"((r)[0]),"=r"((r)[1]),"=r"((r)[2]),"=r"((r)[3]),"=r"((r)[4]),"=r"((r)[5]), \
          "=r"((r)[6]),"=r"((r)[7]),"=r"((r)[8]),"=r"((r)[9]),"=r"((r)[10]),"=r"((r)[11]), \
          "=r"((r)[12]),"=r"((r)[13]),"=r"((r)[14]),"=r"((r)[15]),"=r"((r)[16]),"=r"((r)[17]), \
          "=r"((r)[18]),"=r"((r)[19]),"=r"((r)[20]),"=r"((r)[21]),"=r"((r)[22]),"=r"((r)[23]), \
          "=r"((r)[24]),"=r"((r)[25]),"=r"((r)[26]),"=r"((r)[27]),"=r"((r)[28]),"=r"((r)[29]), \
          "=r"((r)[30]),"=r"((r)[31]) : "r"(a))

static __device__ __forceinline__ uint64_t mkdesc(uint32_t addr) {
    uint64_t d = ((uint64_t)2 << 61) | ((uint64_t)1 << 46) |
                 ((uint64_t)64 << 32) | ((uint64_t)1 << 16);
    return d | ((uint64_t)(addr >> 4) & 0x3FFF);
}

__device__ __forceinline__ void mma_bf16(uint32_t d, uint64_t a, uint64_t b,
                                         uint32_t idesc, unsigned en) {
    uint32_t z = 0;
    asm volatile(
        "{\n\t.reg .pred p;\n\t"
        "setp.ne.u32 p, %5, 0;\n\t"
        "tcgen05.mma.cta_group::1.kind::f16 [%0], %1, %2, %3, {%4, %4, %4, %4}, p;\n\t}"
        :: "r"(d), "l"(a), "l"(b), "r"(idesc), "r"(z), "r"(en) : "memory");
}
#endif  // HAVE_TC

__global__ void __launch_bounds__(256, 1)
#if HAVE_TC
__cluster_dims__(2, 1, 1)
#endif
k_gemm_tc(const __grid_constant__ CUtensorMap tmA,
          const __grid_constant__ CUtensorMap tmB,
          const float* __restrict__ bias, float* __restrict__ out,
          int M, int N, int K) {
#if HAVE_TC
    extern __shared__ char smem[];   // SW128: 1024B-aligned dynamic base; no static smem
    uint32_t sb = (uint32_t)__cvta_generic_to_shared(smem);
    float* red_min = (float*)(smem + 96);
    float* red_max = (float*)(smem + 128);
    int tid = threadIdx.x, wid = tid >> 5, lane = tid & 31;
    uint32_t rank;
    asm("mov.u32 %0, %%cluster_ctarank;" : "=r"(rank));
    int row0 = blockIdx.y << 8, col0 = blockIdx.x << 8;
    int nkt = K >> 6;

    if (wid == 0) {
        uint32_t nc = 512;
        asm volatile("tcgen05.alloc.cta_group::1.sync.aligned.shared::cta.b32 [%0], %1;"
                     :: "r"(sb), "r"(nc) : "memory");
        asm volatile("tcgen05.relinquish_alloc_permit.cta_group::1.sync.aligned;");
    }
    if (tid == 0) {
        #pragma unroll
        for (int s = 0; s < STAGES; s++) {
            MBAR_INIT(sb + 8 + 8 * s, 1);    // full[s]
            MBAR_INIT(sb + 40 + 8 * s, 2);   // empty[s]: both consumers
        }
        MBAR_INIT(sb + 72, 1);               // done
    }
    __syncthreads();
    CLUSTER_SYNC();
    uint32_t tb;
    asm volatile("ld.shared.b32 %0, [%1];" : "=r"(tb) : "r"(sb));
    uint32_t dbar = sb + 72;

    const uint32_t IDESC = (1u << 4) | (1u << 7) | (1u << 10) |
                           (32u << 17) | (8u << 24);   // F32, bf16xbf16, N=256, M=128

    if (tid == 32) {
        for (int ktp = 0; ktp < nkt; ktp++) {
            int b = ktp % STAGES;
            if (ktp >= STAGES)
                MBAR_WAIT(sb + 40 + 8 * b, (unsigned)(((ktp / STAGES) - 1) & 1));
            uint32_t fb = sb + 8 + 8 * b;
            uint32_t sbase = sb + TILE_BASE + b * STAGE_BYTES;
            MBAR_EXPECT_TX(fb, (unsigned)STAGE_BYTES);
            if (rank == 0)
                TMA_2D_MC(sbase, &tmA, ktp << 6, row0, fb, 3);
            TMA_2D(sbase + 32768u, &tmB, ktp << 6, col0, fb);
        }
    } else if (tid == 0) {
        for (int kt = 0; kt < nkt; kt++) {
            int b = kt % STAGES;
            MBAR_WAIT(sb + 8 + 8 * b, (unsigned)((kt / STAGES) & 1));
            uint32_t sbase = sb + TILE_BASE + b * STAGE_BYTES;
            uint64_t dAa = mkdesc(sbase);
            uint64_t dAb = mkdesc(sbase + 16384u);
            uint64_t dB  = mkdesc(sbase + 32768u);
            #pragma unroll
            for (int k = 0; k < 4; k++) {
                unsigned en = (kt > 0 || k > 0) ? 1u : 0u;
                mma_bf16(tb + 0,   dAa + k * 2, dB + k * 2, IDESC, en);
                mma_bf16(tb + 256, dAb + k * 2, dB + k * 2, IDESC, en);
            }
            TC_COMMIT_MC(sb + 40 + 8 * b, 3);
            if (kt == nkt - 1) TC_COMMIT(dbar);
        }
    }

    MBAR_WAIT(dbar, 0u);
    asm volatile("tcgen05.fence::after_thread_sync;" ::: "memory");

    // ---- epilogue: 8 warps = 2 atoms x 4 subpartitions; 256 cols each ----
    int h = wid >> 2, sp = wid & 3;
    int grow = row0 + h * 128 + sp * 32 + lane;
    float sxw = g_xs * g_wsc;
    float xzpf = (float)g_xzpi;
    long long kzz = (long long)K * g_xzpi * g_wzpi;
    float rowcf = (float)((long long)g_wzpi * g_rsx[grow] - kzz);
    float pmin = __int_as_float(0x7f800000), pmax = -pmin;
    float* orow = out + (size_t)grow * N + col0;

    #pragma unroll 1
    for (int cc = 0; cc < 8; cc++) {
        uint32_t r1[32];
        LDTM_X32(r1, tb + (uint32_t)(h * 256 + cc * 32));
        asm volatile("tcgen05.wait::ld.sync.aligned;" ::: "memory");
        int cbase = col0 + cc * 32;
        #pragma unroll
        for (int q = 0; q < 8; q++) {
            float ov[4];
            #pragma unroll
            for (int t = 0; t < 4; t++) {
                int j = q * 4 + t;
                int c = cbase + j;
                float v1 = __uint_as_float(r1[j]);
                float br = v1 - rowcf - xzpf * (float)g_rsw[c];
                float op = br * sxw + bias[c];
                pmin = fminf(pmin, op);
                pmax = fmaxf(pmax, op);
                ov[t] = op;
            }
            *(float4*)(orow + cc * 32 + q * 4) = make_float4(ov[0], ov[1], ov[2], ov[3]);
        }
    }

    #pragma unroll
    for (int o = 16; o > 0; o >>= 1) {
        pmin = fminf(pmin, __shfl_xor_sync(0xffffffffu, pmin, o));
        pmax = fmaxf(pmax, __shfl_xor_sync(0xffffffffu, pmax, o));
    }
    if (lane == 0) { red_min[wid] = pmin; red_max[wid] = pmax; }
    __syncthreads();
    if (tid == 0) {
        #pragma unroll
        for (int i = 1; i < 8; i++) { pmin = fminf(pmin, red_min[i]); pmax = fmaxf(pmax, red_max[i]); }
        atomicMin(&g_keys[4], fkey(pmin));
        atomicMax(&g_keys[5], fkey(pmax));
    }
    __syncthreads();
    CLUSTER_SYNC();
    if (wid == 0) {
        uint32_t nc = 512;
        asm volatile("tcgen05.dealloc.cta_group::1.sync.aligned.b32 %0, %1;"
                     :: "r"(tb), "r"(nc));
    }
    CLUSTER_SYNC();
#endif  // HAVE_TC
}

// ---------------------------------------------------------------------------
// Candidate refine (tc path): exact act min/max near the pre-extremes.
// bf16(qx') x s8(qe) FFMA dot: every product is an exact small int in fp32.
// ---------------------------------------------------------------------------
__global__ void k_cand(const float* __restrict__ out, int M, int N, int K) {
#if HAVE_TC
    float pmin = fdec(g_keys[4]), pmax = fdec(g_keys[5]);
    float ce = g_xs * g_es;
    float xzpf = (float)g_xzpi;
    float sigx = sqrtf((float)g_sq[0] / (float)((long long)M * K));
    float sige = sqrtf((float)g_sq[1] / (float)((long long)N * K));
    float C = 20.0f * ce * sigx * sige * sqrtf((float)K);
    float thi = pmax - 2.0f * C;
    float tlo = pmin + 2.0f * C;

    long long n4 = (long long)M * N / 4;
    const float4* p4 = (const float4*)out;
    float amin = __int_as_float(0x7f800000), amax = -amin;
    bool touched = false;

    for (long long i4 = blockIdx.x * (long long)blockDim.x + threadIdx.x; i4 < n4;
         i4 += (long long)gridDim.x * blockDim.x) {
        float4 v = p4[i4];
        float vv[4] = {v.x, v.y, v.z, v.w};
        #pragma unroll
        for (int t = 0; t < 4; t++) {
            float op = vv[t];
            if (op >= thi || op <= tlo) {
                long long idx = i4 * 4 + t;
                int i = (int)(idx / N);
                int j = (int)(idx - (long long)i * N);
                const __nv_bfloat162* xr = (const __nv_bfloat162*)(g_qxh + (size_t)i * K);
                const char4* er = (const char4*)(g_qe + (size_t)j * K);
                float dp = 0.f;
                for (int k = 0; k < K / 4; k++) {
                    float2 a01 = __bfloat1622float2(xr[2 * k]);
                    float2 a23 = __bfloat1622float2(xr[2 * k + 1]);
                    char4 e = er[k];
                    dp = fmaf(a01.x, (float)e.x, dp);
                    dp = fmaf(a01.y, (float)e.y, dp);
                    dp = fmaf(a23.x, (float)e.z, dp);
                    dp = fmaf(a23.y, (float)e.w, dp);
                }
                float corr = ce * (dp - xzpf * (float)g_rsqe[j]);
                float act = op + corr;
                amin = fminf(amin, act);
                amax = fmaxf(amax, act);
                touched = true;
            }
        }
    }
    if (touched) {
        atomicMin(&g_keys[6], fkey(amin));
        atomicMax(&g_keys[7], fkey(amax));
    }
#endif
}

// ===========================================================================
// Engine B: mma.sync s8 dual-GEMM fallback (baseline pass only)
// ===========================================================================
#define ASTRIDE 80

#if !HAVE_TC
__device__ __forceinline__ void cpa16g(void* smem, const void* gmem) {
    unsigned s = (unsigned)__cvta_generic_to_shared(smem);
    asm volatile("cp.async.cg.shared.global [%0], [%1], 16;\n" :: "r"(s), "l"(gmem));
}
__device__ __forceinline__ void mma_s8(int* d, const int* a, const int* b) {
    asm volatile(
        "mma.sync.aligned.m16n8k32.row.col.s32.s8.s8.s32 "
        "{%0,%1,%2,%3}, {%4,%5,%6,%7}, {%8,%9}, {%0,%1,%2,%3};\n"
        : "+r"(d[0]), "+r"(d[1]), "+r"(d[2]), "+r"(d[3])
        : "r"(a[0]), "r"(a[1]), "r"(a[2]), "r"(a[3]), "r"(b[0]), "r"(b[1]));
}
#endif

__global__ void __launch_bounds__(256) k_gemm_fb(const float* __restrict__ bias,
                                                 float* __restrict__ out,
                                                 int M, int N, int K) {
#if !HAVE_TC
    __shared__ __align__(16) signed char As[2][128 * ASTRIDE];
    __shared__ __align__(16) signed char Bw[2][64 * ASTRIDE];
    __shared__ __align__(16) signed char Be[2][64 * ASTRIDE];

    int tid = threadIdx.x;
    int wid = tid >> 5, lane = tid & 31;
    int wm = wid >> 1, wn = wid & 1;
    int g = lane >> 2, tig = lane & 3;
    int row0 = blockIdx.y << 7, col0 = blockIdx.x << 6;

    int acc1[2][4][4], acc2[2][4][4];
    #pragma unroll
    for (int i = 0; i < 2; i++)
        #pragma unroll
        for (int j = 0; j < 4; j++)
            #pragma unroll
            for (int c = 0; c < 4; c++) { acc1[i][j][c] = 0; acc2[i][j][c] = 0; }

    int nkt = K >> 6;
    int a_r0 = tid >> 2, a_c = (tid & 3) * 16;
    int b_r  = tid >> 2, b_c = (tid & 3) * 16;

    {
        const signed char* gA = g_qx + (size_t)(row0 + a_r0) * K + a_c;
        cpa16g(&As[0][a_r0 * ASTRIDE + a_c], gA);
        cpa16g(&As[0][(a_r0 + 64) * ASTRIDE + a_c], gA + (size_t)64 * K);
        cpa16g(&Bw[0][b_r * ASTRIDE + b_c], g_qw + (size_t)(col0 + b_r) * K + b_c);
        cpa16g(&Be[0][b_r * ASTRIDE + b_c], g_qe + (size_t)(col0 + b_r) * K + b_c);
        asm volatile("cp.async.commit_group;\n");
    }

    #pragma unroll 1
    for (int kt = 0; kt < nkt; kt++) {
        asm volatile("cp.async.wait_group 0;\n");
        __syncthreads();

        if (kt + 1 < nkt) {
            int b = (kt + 1) & 1;
            int k0 = (kt + 1) << 6;
            const signed char* gA = g_qx + (size_t)(row0 + a_r0) * K + k0 + a_c;
            cpa16g(&As[b][a_r0 * ASTRIDE + a_c], gA);
            cpa16g(&As[b][(a_r0 + 64) * ASTRIDE + a_c], gA + (size_t)64 * K);
            cpa16g(&Bw[b][b_r * ASTRIDE + b_c], g_qw + (size_t)(col0 + b_r) * K + k0 + b_c);
            cpa16g(&Be[b][b_r * ASTRIDE + b_c], g_qe + (size_t)(col0 + b_r) * K + k0 + b_c);
            asm volatile("cp.async.commit_group;\n");
        }

        const signed char* Ab  = As[kt & 1];
        const signed char* Bwb = Bw[kt & 1];
        const signed char* Beb = Be[kt & 1];

        #pragma unroll
        for (int kseg = 0; kseg < 2; kseg++) {
            int koff = kseg * 32 + tig * 4;
            int a[2][4];
            #pragma unroll
            for (int mi = 0; mi < 2; mi++) {
                int r0 = wm * 32 + mi * 16 + g;
                a[mi][0] = *(const int*)&Ab[r0 * ASTRIDE + koff];
                a[mi][1] = *(const int*)&Ab[(r0 + 8) * ASTRIDE + koff];
                a[mi][2] = *(const int*)&Ab[r0 * ASTRIDE + koff + 16];
                a[mi][3] = *(const int*)&Ab[(r0 + 8) * ASTRIDE + koff + 16];
            }
            int bw[4][2], be2[4][2];
            #pragma unroll
            for (int ni = 0; ni < 4; ni++) {
                int rn = wn * 32 + ni * 8 + g;
                bw[ni][0]  = *(const int*)&Bwb[rn * ASTRIDE + koff];
                bw[ni][1]  = *(const int*)&Bwb[rn * ASTRIDE + koff + 16];
                be2[ni][0] = *(const int*)&Beb[rn * ASTRIDE + koff];
                be2[ni][1] = *(const int*)&Beb[rn * ASTRIDE + koff + 16];
            }
            #pragma unroll
            for (int mi = 0; mi < 2; mi++)
                #pragma unroll
                for (int ni = 0; ni < 4; ni++) {
                    mma_s8(acc1[mi][ni], a[mi], bw[ni]);
                    mma_s8(acc2[mi][ni], a[mi], be2[ni]);
                }
        }
        __syncthreads();
    }

    float sxw = g_xs * g_wsc;
    float ce  = g_xs * g_es;
    int xzpi = g_xzpi, wzpi = g_wzpi;
    long long kzz = (long long)K * xzpi * wzpi;
    float amin = __int_as_float(0x7f800000), amax = -amin;

    int   rsw_[4][2], rsqe_[4][2];
    float bias_[4][2];
    int cbase[4];
    #pragma unroll
    for (int ni = 0; ni < 4; ni++) {
        int c0 = col0 + wn * 32 + ni * 8 + tig * 2;
        cbase[ni] = c0;
        rsw_[ni][0] = g_rsw[c0];  rsw_[ni][1] = g_rsw[c0 + 1];
        rsqe_[ni][0] = g_rsqe[c0]; rsqe_[ni][1] = g_rsqe[c0 + 1];
        float2 bv = *(const float2*)(bias + c0);
        bias_[ni][0] = bv.x; bias_[ni][1] = bv.y;
    }

    #pragma unroll
    for (int mi = 0; mi < 2; mi++) {
        #pragma unroll
        for (int rr = 0; rr < 2; rr++) {
            int row = row0 + wm * 32 + mi * 16 + rr * 8 + g;
            long long rowc = (long long)wzpi * g_rsx[row] - kzz;
            #pragma unroll
            for (int ni = 0; ni < 4; ni++) {
                float ov[2];
                #pragma unroll
                for (int cc = 0; cc < 2; cc++) {
                    int v1 = acc1[mi][ni][rr * 2 + cc];
                    int v2 = acc2[mi][ni][rr * 2 + cc];
                    long long br = (long long)v1 - rowc - (long long)xzpi * rsw_[ni][cc];
                    float op = (float)br * sxw + bias_[ni][cc];
                    float act = op + ce * (float)((long long)v2 - (long long)xzpi * rsqe_[ni][cc]);
                    amin = fminf(amin, act);
                    amax = fmaxf(amax, act);
                    ov[cc] = op;
                }
                *(float2*)(out + (size_t)row * N + cbase[ni]) = make_float2(ov[0], ov[1]);
            }
        }
    }

    #pragma unroll
    for (int o = 16; o > 0; o >>= 1) {
        amin = fminf(amin, __shfl_xor_sync(0xffffffffu, amin, o));
        amax = fmaxf(amax, __shfl_xor_sync(0xffffffffu, amax, o));
    }
    __shared__ float smin[8], smax[8];
    if (lane == 0) { smin[wid] = amin; smax[wid] = amax; }
    __syncthreads();
    if (tid == 0) {
        #pragma unroll
        for (int i = 1; i < 8; i++) { amin = fminf(amin, smin[i]); amax = fmaxf(amax, smax[i]); }
        atomicMin(&g_keys[6], fkey(amin));
        atomicMax(&g_keys[7], fkey(amax));
    }
#endif  // !HAVE_TC
}

__global__ void k_scales2() {
    float amin = fdec(g_keys[6]), amax = fdec(g_keys[7]);
    float as = (amax - amin) / 255.0f;
    g_as = as;
    g_azp = rintf(0.0f - amin / as);
}

__global__ void k_requant(float* __restrict__ out, long long n4) {
    float as = g_as, azp = g_azp;
    float4* p = (float4*)out;
    for (long long i = blockIdx.x * (long long)blockDim.x + threadIdx.x; i < n4;
         i += (long long)gridDim.x * blockDim.x) {
        float4 v = p[i];
        v.x = (fminf(255.f, fmaxf(0.f, rintf(v.x / as + azp))) - azp) * as;
        v.y = (fminf(255.f, fmaxf(0.f, rintf(v.y / as + azp))) - azp) * as;
        v.z = (fminf(255.f, fmaxf(0.f, rintf(v.z / as + azp))) - azp) * as;
        v.w = (fminf(255.f, fmaxf(0.f, rintf(v.w / as + azp))) - azp) * as;
        p[i] = v;
    }
}

// ---------------------------------------------------------------------------
// Host: tensor-map encoding via driver entry point (no -lcuda needed).
// ---------------------------------------------------------------------------
typedef CUresult (*encode_fn_t)(
    CUtensorMap*, CUtensorMapDataType, cuuint32_t, void*,
    const cuuint64_t*, const cuuint64_t*, const cuuint32_t*, const cuuint32_t*,
    CUtensorMapInterleave, CUtensorMapSwizzle, CUtensorMapL2promotion,
    CUtensorMapFloatOOBfill);

static void encode_bf16_2d(encode_fn_t fn, CUtensorMap* m, void* base,
                           unsigned long long rows, int K) {
    cuuint64_t dims[2]    = {(cuuint64_t)K, (cuuint64_t)rows};
    cuuint64_t strides[1] = {(cuuint64_t)K * 2};
    cuuint32_t box[2]     = {64u, 256u};
    cuuint32_t es[2]      = {1u, 1u};
    fn(m, CU_TENSOR_MAP_DATA_TYPE_BFLOAT16, 2, base, dims, strides, box, es,
       CU_TENSOR_MAP_INTERLEAVE_NONE, CU_TENSOR_MAP_SWIZZLE_128B,
       CU_TENSOR_MAP_L2_PROMOTION_L2_128B, CU_TENSOR_MAP_FLOAT_OOB_FILL_NONE);
}

extern "C" void kernel_launch(void* const* d_in, const int* in_sizes, int n_in,
                              void* d_out, int out_size) {
    const float* x = (const float*)d_in[0];
    const float* w = (const float*)d_in[1];
    const float* b = (const float*)d_in[2];
    float* out = (float*)d_out;

    int N = in_sizes[2];
    int K = in_sizes[1] / N;
    int M = in_sizes[0] / K;
    if (M > MAXM || N > MAXN || K > MAXK) return;
    if ((M & 255) || (N & 511) || (K & 127)) return;

    cudaFuncSetAttribute(k_gemm_tc, cudaFuncAttributeMaxDynamicSharedMemorySize, SMEM_TC);

    // Engine detection: inactive engine's kernel is an empty stub (few regs).
    int tc_live = 1, fb_live = 1;
    cudaFuncAttributes fa{};
    if (cudaFuncGetAttributes(&fa, (const void*)k_gemm_tc) == cudaSuccess) {
        if (fa.numRegs >= 40) fb_live = 0; else tc_live = 0;
    }

    encode_fn_t efn = nullptr;
    cudaDriverEntryPointQueryResult qres;
    cudaGetDriverEntryPoint("cuTensorMapEncodeTiled", (void**)&efn,
                            cudaEnableDefault, &qres);
    CUtensorMap tmA, tmB;
    void* pA = nullptr; void* pB = nullptr;
    cudaGetSymbolAddress(&pA, g_qxh);
    cudaGetSymbolAddress(&pB, g_qwh);
    if (efn && pA && pB) {
        encode_bf16_2d(efn, &tmA, pA, (unsigned long long)M, K);
        encode_bf16_2d(efn, &tmB, pB, (unsigned long long)N, K);
    } else if (tc_live) {
        return;
    }

    k_init<<<1, 32>>>();
    k_minmax2<<<864, 256>>>(x, (long long)M * K / 4, w, (long long)N * K / 4, 576);
    k_scales1<<<1, 1>>>();
    k_quant<<<M + N, 256>>>(x, w, M, K);

    if (tc_live) {
        dim3 grid_tc(N / 256, M / 256);
        k_gemm_tc<<<grid_tc, 256, SMEM_TC>>>(tmA, tmB, b, out, M, N, K);
        k_cand<<<1184, 256>>>(out, M, N, K);
    }
    if (fb_live) {
        dim3 grid_fb(N / 64, M / 128);
        k_gemm_fb<<<grid_fb, 256>>>(b, out, M, N, K);
    }
    k_scales2<<<1, 1>>>();
    k_requant<<<4096, 256>>>(out, (long long)M * N / 4);
}

// round 16
// speedup vs baseline: 1.1756x; 1.1756x over previous
#include <cuda_runtime.h>
#include <cuda_bf16.h>
#include <cuda.h>
#include <cstdint>

// ---------------------------------------------------------------------------
// QLinear, round 16 = round 14 (best, 468us) + ONE change:
//   fp division -> precomputed reciprocal multiply in k_quant / k_requant.
// Everything else byte-identical to round 14 (incl. dp4a k_cand + qx stores).
// ---------------------------------------------------------------------------

#if defined(__CUDA_ARCH__) && (__CUDA_ARCH__ == 1030) && \
    (defined(__CUDA_ARCH_FEAT_SM103_ALL) || \
     (defined(__CUDA_ARCH_SPECIFIC__) && (__CUDA_ARCH_SPECIFIC__ == 1030)) || \
     (defined(__CUDA_ARCH_FAMILY_SPECIFIC__) && (__CUDA_ARCH_FAMILY_SPECIFIC__ == 1030)))
#define HAVE_TC 1
#else
#define HAVE_TC 0
#endif

#define MAXM 8192
#define MAXN 4096
#define MAXK 4096

__device__ signed char    g_qx [(size_t)MAXM * MAXK];
__device__ signed char    g_qw [(size_t)MAXN * MAXK];   // fallback only
__device__ signed char    g_qe [(size_t)MAXN * MAXK];
__device__ __nv_bfloat16  g_qxh[(size_t)MAXM * MAXK];
__device__ __nv_bfloat16  g_qwh[(size_t)MAXN * MAXK];
__device__ int   g_rsx [MAXM];
__device__ int   g_rsw [MAXN];
__device__ int   g_rsqe[MAXN];
__device__ unsigned long long g_sq[2];
__device__ unsigned g_keys[8];  // xmin,xmax,wmin,wmax, pre_min,pre_max, act_min,act_max
__device__ float g_xs, g_xzp, g_wsc, g_wzp, g_es, g_as, g_azp;
__device__ float g_ixs, g_iws, g_ies, g_ias;   // reciprocals
__device__ int   g_xzpi, g_wzpi;

__device__ __forceinline__ unsigned fkey(float v) {
    unsigned u = __float_as_uint(v);
    return (u & 0x80000000u) ? ~u : (u | 0x80000000u);
}
__device__ __forceinline__ float fdec(unsigned k) {
    unsigned u = (k & 0x80000000u) ? (k & 0x7FFFFFFFu) : ~k;
    return __uint_as_float(u);
}

// ---- prologue kernels -------------------------------------------------------
__global__ void k_init() {
    if (threadIdx.x == 0) {
        g_keys[0] = 0xFFFFFFFFu; g_keys[1] = 0u;
        g_keys[2] = 0xFFFFFFFFu; g_keys[3] = 0u;
        g_keys[4] = 0xFFFFFFFFu; g_keys[5] = 0u;
        g_keys[6] = 0xFFFFFFFFu; g_keys[7] = 0u;
        g_sq[0] = 0ull; g_sq[1] = 0ull;
    }
}

// Fused min/max over x (blocks [0,gx)) and w (blocks [gx,grid)).
__global__ void k_minmax2(const float* __restrict__ x, long long n4x,
                          const float* __restrict__ w, long long n4w, int gx) {
    const float4* p4;
    long long n4; int imin, imax, nb, bid;
    if (blockIdx.x < (unsigned)gx) {
        p4 = (const float4*)x; n4 = n4x; imin = 0; imax = 1;
        nb = gx; bid = blockIdx.x;
    } else {
        p4 = (const float4*)w; n4 = n4w; imin = 2; imax = 3;
        nb = gridDim.x - gx; bid = blockIdx.x - gx;
    }
    float lmin = __int_as_float(0x7f800000);
    float lmax = -lmin;
    for (long long i = bid * (long long)blockDim.x + threadIdx.x; i < n4;
         i += (long long)nb * blockDim.x) {
        float4 v = p4[i];
        lmin = fminf(lmin, fminf(fminf(v.x, v.y), fminf(v.z, v.w)));
        lmax = fmaxf(lmax, fmaxf(fmaxf(v.x, v.y), fmaxf(v.z, v.w)));
    }
    #pragma unroll
    for (int o = 16; o > 0; o >>= 1) {
        lmin = fminf(lmin, __shfl_xor_sync(0xffffffffu, lmin, o));
        lmax = fmaxf(lmax, __shfl_xor_sync(0xffffffffu, lmax, o));
    }
    __shared__ float smin[8], smax[8];
    int w8 = threadIdx.x >> 5;
    if ((threadIdx.x & 31) == 0) { smin[w8] = lmin; smax[w8] = lmax; }
    __syncthreads();
    if (threadIdx.x == 0) {
        int nw = (int)(blockDim.x >> 5);
        for (int i = 1; i < nw; i++) { lmin = fminf(lmin, smin[i]); lmax = fmaxf(lmax, smax[i]); }
        atomicMin(&g_keys[imin], fkey(lmin));
        atomicMax(&g_keys[imax], fkey(lmax));
    }
}

__global__ void k_scales1() {
    float xmin = fdec(g_keys[0]), xmax = fdec(g_keys[1]);
    float wmin = fdec(g_keys[2]), wmax = fdec(g_keys[3]);
    float xs = (xmax - xmin) / 255.0f;
    float xzp = rintf(0.0f - xmin / xs);
    g_xs = xs; g_xzp = xzp; g_xzpi = (int)xzp - 128;
    float ws = (wmax - wmin) / 255.0f;
    float wzp = rintf(-128.0f - wmin / ws);
    g_wsc = ws; g_wzp = wzp; g_wzpi = (int)wzp;
    float es = ws / 127.0f;
    g_es = es;
    g_ixs = 1.0f / xs;
    g_iws = 1.0f / ws;
    g_ies = 1.0f / es;
}

// Fused quantization: blocks [0,M) quantize x rows; blocks [M,M+N) quantize w rows.
__global__ void k_quant(const float* __restrict__ x, const float* __restrict__ w,
                        int M, int K) {
    __shared__ int ss[8], se[8];
    __shared__ long long sqs[8];
    if ((int)blockIdx.x < M) {
        int row = blockIdx.x;
        const float* xr = x + (size_t)row * K;
        signed char* qr = g_qx + (size_t)row * K;
        __nv_bfloat16* hr = g_qxh + (size_t)row * K;
        float ixs = g_ixs, xzp = g_xzp;
        int sum = 0; long long sq = 0;
        for (int k = threadIdx.x * 4; k < K; k += blockDim.x * 4) {
            float4 v = *(const float4*)(xr + k);
            int q0 = (int)fminf(255.f, fmaxf(0.f, rintf(fmaf(v.x, ixs, xzp)))) - 128;
            int q1 = (int)fminf(255.f, fmaxf(0.f, rintf(fmaf(v.y, ixs, xzp)))) - 128;
            int q2 = (int)fminf(255.f, fmaxf(0.f, rintf(fmaf(v.z, ixs, xzp)))) - 128;
            int q3 = (int)fminf(255.f, fmaxf(0.f, rintf(fmaf(v.w, ixs, xzp)))) - 128;
            sum += q0 + q1 + q2 + q3;
            sq  += q0 * q0 + q1 * q1 + q2 * q2 + q3 * q3;
            unsigned pk = (unsigned)(q0 & 0xFF) | ((unsigned)(q1 & 0xFF) << 8) |
                          ((unsigned)(q2 & 0xFF) << 16) | ((unsigned)(q3 & 0xFF) << 24);
            *(unsigned*)(qr + k) = pk;
#if HAVE_TC
            *(__nv_bfloat162*)(hr + k)     = __floats2bfloat162_rn((float)q0, (float)q1);
            *(__nv_bfloat162*)(hr + k + 2) = __floats2bfloat162_rn((float)q2, (float)q3);
#endif
        }
        #pragma unroll
        for (int o = 16; o > 0; o >>= 1) {
            sum += __shfl_xor_sync(0xffffffffu, sum, o);
            sq  += __shfl_xor_sync(0xffffffffu, sq, o);
        }
        if ((threadIdx.x & 31) == 0) { ss[threadIdx.x >> 5] = sum; sqs[threadIdx.x >> 5] = sq; }
        __syncthreads();
        if (threadIdx.x == 0) {
            int t = 0; long long tq = 0; int nw = (int)(blockDim.x >> 5);
            for (int i = 0; i < nw; i++) { t += ss[i]; tq += sqs[i]; }
            g_rsx[row] = t;
            atomicAdd(&g_sq[0], (unsigned long long)tq);
        }
    } else {
        int row = blockIdx.x - M;
        const float* wr = w + (size_t)row * K;
        signed char* er = g_qe + (size_t)row * K;
        __nv_bfloat16* qh = g_qwh + (size_t)row * K;
#if !HAVE_TC
        signed char* qr = g_qw + (size_t)row * K;
#endif
        float iws = g_iws, ws = g_wsc, wzp = g_wzp, ies = g_ies;
        int isum = 0, esum = 0; long long esq = 0;
        for (int k = threadIdx.x * 4; k < K; k += blockDim.x * 4) {
            float4 v = *(const float4*)(wr + k);
            float qf[4];
            qf[0] = fminf(127.f, fmaxf(-128.f, rintf(fmaf(v.x, iws, wzp))));
            qf[1] = fminf(127.f, fmaxf(-128.f, rintf(fmaf(v.y, iws, wzp))));
            qf[2] = fminf(127.f, fmaxf(-128.f, rintf(fmaf(v.z, iws, wzp))));
            qf[3] = fminf(127.f, fmaxf(-128.f, rintf(fmaf(v.w, iws, wzp))));
            float ev[4];
            ev[0] = v.x - (qf[0] - wzp) * ws;
            ev[1] = v.y - (qf[1] - wzp) * ws;
            ev[2] = v.z - (qf[2] - wzp) * ws;
            ev[3] = v.w - (qf[3] - wzp) * ws;
            int q[4], qe[4];
            #pragma unroll
            for (int j = 0; j < 4; j++) {
                q[j]  = (int)qf[j];
                qe[j] = (int)fminf(127.f, fmaxf(-127.f, rintf(ev[j] * ies)));
                isum += q[j]; esum += qe[j]; esq += qe[j] * qe[j];
            }
            unsigned pe = (unsigned)(qe[0] & 0xFF) | ((unsigned)(qe[1] & 0xFF) << 8) |
                          ((unsigned)(qe[2] & 0xFF) << 16) | ((unsigned)(qe[3] & 0xFF) << 24);
            *(unsigned*)(er + k) = pe;
#if HAVE_TC
            *(__nv_bfloat162*)(qh + k)     = __floats2bfloat162_rn((float)q[0], (float)q[1]);
            *(__nv_bfloat162*)(qh + k + 2) = __floats2bfloat162_rn((float)q[2], (float)q[3]);
#else
            unsigned pq = (unsigned)(q[0] & 0xFF) | ((unsigned)(q[1] & 0xFF) << 8) |
                          ((unsigned)(q[2] & 0xFF) << 16) | ((unsigned)(q[3] & 0xFF) << 24);
            *(unsigned*)(qr + k) = pq;
#endif
        }
        #pragma unroll
        for (int o = 16; o > 0; o >>= 1) {
            isum += __shfl_xor_sync(0xffffffffu, isum, o);
            esum += __shfl_xor_sync(0xffffffffu, esum, o);
            esq  += __shfl_xor_sync(0xffffffffu, esq, o);
        }
        if ((threadIdx.x & 31) == 0) {
            ss[threadIdx.x >> 5] = isum; se[threadIdx.x >> 5] = esum;
            sqs[threadIdx.x >> 5] = esq;
        }
        __syncthreads();
        if (threadIdx.x == 0) {
            int ti = 0, te = 0; long long tq = 0; int nw = (int)(blockDim.x >> 5);
            for (int i = 0; i < nw; i++) { ti += ss[i]; te += se[i]; tq += sqs[i]; }
            g_rsw[row] = ti; g_rsqe[row] = te;
            atomicAdd(&g_sq[1], (unsigned long long)tq);
        }
    }
}

// ===========================================================================
// Engine A: tcgen05 cg1, tile 256Mx256N, TMA-fed, 3 stages x 64KB,
// cluster(2,1,1) A-multicast. Proven round-10/11/14 structure, unchanged.
// ===========================================================================
#define STAGES      3
#define STAGE_BYTES 65536
#define TILE_BASE   1024
#define SMEM_TC     (TILE_BASE + STAGES * STAGE_BYTES)

#if HAVE_TC
#define MBAR_INIT(addr, cnt) \
    asm volatile("mbarrier.init.shared.b64 [%0], %1;" :: "r"(addr), "r"(cnt) : "memory")

#define MBAR_WAIT(addr, ph) do {                                              \
    unsigned _m = (addr), _p = (ph), _d;                                      \
    asm volatile("{\n\t.reg .pred p;\n\t"                                     \
        "mbarrier.try_wait.parity.acquire.cta.shared::cta.b64 p, [%1], %2;\n\t" \
        "selp.b32 %0, 1, 0, p;\n\t}" : "=r"(_d) : "r"(_m), "r"(_p) : "memory"); \
    if (!_d) {                                                                \
        asm volatile("{\n\t.reg .pred P1;\n\t"                                \
            "W%=:\n\t"                                                        \
            "mbarrier.try_wait.parity.acquire.cta.shared::cta.b64 P1, [%0], %1, 0x989680;\n\t" \
            "@P1 bra.uni D%=;\n\t"                                            \
            "bra.uni W%=;\n\t"                                                \
            "D%=:\n\t}" :: "r"(_m), "r"(_p) : "memory");                      \
    }                                                                         \
} while (0)

#define MBAR_EXPECT_TX(addr, bytes) \
    asm volatile("mbarrier.arrive.expect_tx.shared.b64 _, [%0], %1;" \
                 :: "r"(addr), "r"(bytes) : "memory")

#define TC_COMMIT(addr) \
    asm volatile("tcgen05.commit.cta_group::1.mbarrier::arrive::one.shared::cluster.b64 [%0];" \
                 :: "r"(addr) : "memory")

#define TC_COMMIT_MC(addr, mask) \
    asm volatile("tcgen05.commit.cta_group::1.mbarrier::arrive::one.shared::cluster.multicast::cluster.b64 [%0], %1;" \
                 :: "r"(addr), "h"((unsigned short)(mask)) : "memory")

#define TMA_2D(smem, map, cx, cy, mbar) \
    asm volatile("cp.async.bulk.tensor.2d.shared::cta.global.tile.mbarrier::complete_tx::bytes " \
                 "[%0], [%1, {%2, %3}], [%4];" \
                 :: "r"(smem), "l"(map), "r"(cx), "r"(cy), "r"(mbar) : "memory")

#define TMA_2D_MC(smem, map, cx, cy, mbar, mask) \
    asm volatile("cp.async.bulk.tensor.2d.shared::cluster.global.tile.mbarrier::complete_tx::bytes.multicast::cluster " \
                 "[%0], [%1, {%2, %3}], [%4], %5;" \
                 :: "r"(smem), "l"(map), "r"(cx), "r"(cy), "r"(mbar), \
                    "h"((unsigned short)(mask)) : "memory")

#define CLUSTER_SYNC() do { \
    asm volatile("barrier.cluster.arrive.aligned;" ::: "memory"); \
    asm volatile("barrier.cluster.wait.aligned;" ::: "memory"); \
} while (0)

#define LDTM_X32(r, a) \
    asm volatile("tcgen05.ld.sync.aligned.32x32b.x32.b32 " \
        "{%0,%1,%2,%3,%4,%5,%6,%7,%8,%9,%10,%11,%12,%13,%14,%15," \
        "%16,%17,%18,%19,%20,%21,%22,%23,%24,%25,%26,%27,%28,%29,%30,%31}, [%32];" \
        : "=r"((r)[0]),"=r"((r)[1]),"=r"((r)[2]),"=r"((r)[3]),"=r"((r)[4]),"=r"((r)[5]), \
          "=r"((r)[6]),"=r"((r)[7]),"=r"((r)[8]),"=r"((r)[9]),"=r"((r)[10]),"=r"((r)[11]), \
          "=r"((r)[12]),"=r"((r)[13]),"=r"((r)[14]),"=r"((r)[15]),"=r"((r)[16]),"=r"((r)[17]), \
          "=r"((r)[18]),"=r"((r)[19]),"=r"((r)[20]),"=r"((r)[21]),"=r"((r)[22]),"=r"((r)[23]), \
          "=r"((r)[24]),"=r"((r)[25]),"=r"((r)[26]),"=r"((r)[27]),"=r"((r)[28]),"=r"((r)[29]), \
          "=r"((r)[30]),"=r"((r)[31]) : "r"(a))

static __device__ __forceinline__ uint64_t mkdesc(uint32_t addr) {
    uint64_t d = ((uint64_t)2 << 61) | ((uint64_t)1 << 46) |
                 ((uint64_t)64 << 32) | ((uint64_t)1 << 16);
    return d | ((uint64_t)(addr >> 4) & 0x3FFF);
}

__device__ __forceinline__ void mma_bf16(uint32_t d, uint64_t a, uint64_t b,
                                         uint32_t idesc, unsigned en) {
    uint32_t z = 0;
    asm volatile(
        "{\n\t.reg .pred p;\n\t"
        "setp.ne.u32 p, %5, 0;\n\t"
        "tcgen05.mma.cta_group::1.kind::f16 [%0], %1, %2, %3, {%4, %4, %4, %4}, p;\n\t}"
        :: "r"(d), "l"(a), "l"(b), "r"(idesc), "r"(z), "r"(en) : "memory");
}
#endif  // HAVE_TC

__global__ void __launch_bounds__(256, 1)
#if HAVE_TC
__cluster_dims__(2, 1, 1)
#endif
k_gemm_tc(const __grid_constant__ CUtensorMap tmA,
          const __grid_constant__ CUtensorMap tmB,
          const float* __restrict__ bias, float* __restrict__ out,
          int M, int N, int K) {
#if HAVE_TC
    extern __shared__ char smem[];   // SW128: 1024B-aligned dynamic base; no static smem
    uint32_t sb = (uint32_t)__cvta_generic_to_shared(smem);
    float* red_min = (float*)(smem + 96);
    float* red_max = (float*)(smem + 128);
    int tid = threadIdx.x, wid = tid >> 5, lane = tid & 31;
    uint32_t rank;
    asm("mov.u32 %0, %%cluster_ctarank;" : "=r"(rank));
    int row0 = blockIdx.y << 8, col0 = blockIdx.x << 8;
    int nkt = K >> 6;

    if (wid == 0) {
        uint32_t nc = 512;
        asm volatile("tcgen05.alloc.cta_group::1.sync.aligned.shared::cta.b32 [%0], %1;"
                     :: "r"(sb), "r"(nc) : "memory");
        asm volatile("tcgen05.relinquish_alloc_permit.cta_group::1.sync.aligned;");
    }
    if (tid == 0) {
        #pragma unroll
        for (int s = 0; s < STAGES; s++) {
            MBAR_INIT(sb + 8 + 8 * s, 1);    // full[s]
            MBAR_INIT(sb + 40 + 8 * s, 2);   // empty[s]: both consumers
        }
        MBAR_INIT(sb + 72, 1);               // done
    }
    __syncthreads();
    CLUSTER_SYNC();
    uint32_t tb;
    asm volatile("ld.shared.b32 %0, [%1];" : "=r"(tb) : "r"(sb));
    uint32_t dbar = sb + 72;

    const uint32_t IDESC = (1u << 4) | (1u << 7) | (1u << 10) |
                           (32u << 17) | (8u << 24);   // F32, bf16xbf16, N=256, M=128

    if (tid == 32) {
        for (int ktp = 0; ktp < nkt; ktp++) {
            int b = ktp % STAGES;
            if (ktp >= STAGES)
                MBAR_WAIT(sb + 40 + 8 * b, (unsigned)(((ktp / STAGES) - 1) & 1));
            uint32_t fb = sb + 8 + 8 * b;
            uint32_t sbase = sb + TILE_BASE + b * STAGE_BYTES;
            MBAR_EXPECT_TX(fb, (unsigned)STAGE_BYTES);
            if (rank == 0)
                TMA_2D_MC(sbase, &tmA, ktp << 6, row0, fb, 3);
            TMA_2D(sbase + 32768u, &tmB, ktp << 6, col0, fb);
        }
    } else if (tid == 0) {
        for (int kt = 0; kt < nkt; kt++) {
            int b = kt % STAGES;
            MBAR_WAIT(sb + 8 + 8 * b, (unsigned)((kt / STAGES) & 1));
            uint32_t sbase = sb + TILE_BASE + b * STAGE_BYTES;
            uint64_t dAa = mkdesc(sbase);
            uint64_t dAb = mkdesc(sbase + 16384u);
            uint64_t dB  = mkdesc(sbase + 32768u);
            #pragma unroll
            for (int k = 0; k < 4; k++) {
                unsigned en = (kt > 0 || k > 0) ? 1u : 0u;
                mma_bf16(tb + 0,   dAa + k * 2, dB + k * 2, IDESC, en);
                mma_bf16(tb + 256, dAb + k * 2, dB + k * 2, IDESC, en);
            }
            TC_COMMIT_MC(sb + 40 + 8 * b, 3);
            if (kt == nkt - 1) TC_COMMIT(dbar);
        }
    }

    MBAR_WAIT(dbar, 0u);
    asm volatile("tcgen05.fence::after_thread_sync;" ::: "memory");

    // ---- epilogue: 8 warps = 2 atoms x 4 subpartitions; 256 cols each ----
    int h = wid >> 2, sp = wid & 3;
    int grow = row0 + h * 128 + sp * 32 + lane;
    float sxw = g_xs * g_wsc;
    float xzpf = (float)g_xzpi;
    long long kzz = (long long)K * g_xzpi * g_wzpi;
    float rowcf = (float)((long long)g_wzpi * g_rsx[grow] - kzz);
    float pmin = __int_as_float(0x7f800000), pmax = -pmin;
    float* orow = out + (size_t)grow * N + col0;

    #pragma unroll 1
    for (int cc = 0; cc < 8; cc++) {
        uint32_t r1[32];
        LDTM_X32(r1, tb + (uint32_t)(h * 256 + cc * 32));
        asm volatile("tcgen05.wait::ld.sync.aligned;" ::: "memory");
        int cbase = col0 + cc * 32;
        #pragma unroll
        for (int q = 0; q < 8; q++) {
            float ov[4];
            #pragma unroll
            for (int t = 0; t < 4; t++) {
                int j = q * 4 + t;
                int c = cbase + j;
                float v1 = __uint_as_float(r1[j]);
                float br = v1 - rowcf - xzpf * (float)g_rsw[c];
                float op = br * sxw + bias[c];
                pmin = fminf(pmin, op);
                pmax = fmaxf(pmax, op);
                ov[t] = op;
            }
            *(float4*)(orow + cc * 32 + q * 4) = make_float4(ov[0], ov[1], ov[2], ov[3]);
        }
    }

    #pragma unroll
    for (int o = 16; o > 0; o >>= 1) {
        pmin = fminf(pmin, __shfl_xor_sync(0xffffffffu, pmin, o));
        pmax = fmaxf(pmax, __shfl_xor_sync(0xffffffffu, pmax, o));
    }
    if (lane == 0) { red_min[wid] = pmin; red_max[wid] = pmax; }
    __syncthreads();
    if (tid == 0) {
        #pragma unroll
        for (int i = 1; i < 8; i++) { pmin = fminf(pmin, red_min[i]); pmax = fmaxf(pmax, red_max[i]); }
        atomicMin(&g_keys[4], fkey(pmin));
        atomicMax(&g_keys[5], fkey(pmax));
    }
    __syncthreads();
    CLUSTER_SYNC();
    if (wid == 0) {
        uint32_t nc = 512;
        asm volatile("tcgen05.dealloc.cta_group::1.sync.aligned.b32 %0, %1;"
                     :: "r"(tb), "r"(nc));
    }
    CLUSTER_SYNC();
#endif  // HAVE_TC
}

// ---------------------------------------------------------------------------
// Candidate refine (tc path): exact act min/max near the pre-extremes (dp4a).
// ---------------------------------------------------------------------------
__global__ void k_cand(const float* __restrict__ out, int M, int N, int K) {
#if HAVE_TC
    float pmin = fdec(g_keys[4]), pmax = fdec(g_keys[5]);
    float ce = g_xs * g_es;
    float xzpf = (float)g_xzpi;
    float sigx = sqrtf((float)g_sq[0] / (float)((long long)M * K));
    float sige = sqrtf((float)g_sq[1] / (float)((long long)N * K));
    float C = 20.0f * ce * sigx * sige * sqrtf((float)K);
    float thi = pmax - 2.0f * C;
    float tlo = pmin + 2.0f * C;

    long long n4 = (long long)M * N / 4;
    const float4* p4 = (const float4*)out;
    float amin = __int_as_float(0x7f800000), amax = -amin;
    bool touched = false;

    for (long long i4 = blockIdx.x * (long long)blockDim.x + threadIdx.x; i4 < n4;
         i4 += (long long)gridDim.x * blockDim.x) {
        float4 v = p4[i4];
        float vv[4] = {v.x, v.y, v.z, v.w};
        #pragma unroll
        for (int t = 0; t < 4; t++) {
            float op = vv[t];
            if (op >= thi || op <= tlo) {
                long long idx = i4 * 4 + t;
                int i = (int)(idx / N);
                int j = (int)(idx - (long long)i * N);
                const int* xr = (const int*)(g_qx + (size_t)i * K);
                const int* er = (const int*)(g_qe + (size_t)j * K);
                int dp = 0;
                for (int k = 0; k < K / 4; k += 4) {
                    dp = __dp4a(xr[k],     er[k],     dp);
                    dp = __dp4a(xr[k + 1], er[k + 1], dp);
                    dp = __dp4a(xr[k + 2], er[k + 2], dp);
                    dp = __dp4a(xr[k + 3], er[k + 3], dp);
                }
                float corr = ce * ((float)dp - xzpf * (float)g_rsqe[j]);
                float act = op + corr;
                amin = fminf(amin, act);
                amax = fmaxf(amax, act);
                touched = true;
            }
        }
    }
    if (touched) {
        atomicMin(&g_keys[6], fkey(amin));
        atomicMax(&g_keys[7], fkey(amax));
    }
#endif
}

// ===========================================================================
// Engine B: mma.sync s8 dual-GEMM fallback (baseline pass only)
// ===========================================================================
#define ASTRIDE 80

#if !HAVE_TC
__device__ __forceinline__ void cpa16g(void* smem, const void* gmem) {
    unsigned s = (unsigned)__cvta_generic_to_shared(smem);
    asm volatile("cp.async.cg.shared.global [%0], [%1], 16;\n" :: "r"(s), "l"(gmem));
}
__device__ __forceinline__ void mma_s8(int* d, const int* a, const int* b) {
    asm volatile(
        "mma.sync.aligned.m16n8k32.row.col.s32.s8.s8.s32 "
        "{%0,%1,%2,%3}, {%4,%5,%6,%7}, {%8,%9}, {%0,%1,%2,%3};\n"
        : "+r"(d[0]), "+r"(d[1]), "+r"(d[2]), "+r"(d[3])
        : "r"(a[0]), "r"(a[1]), "r"(a[2]), "r"(a[3]), "r"(b[0]), "r"(b[1]));
}
#endif

__global__ void __launch_bounds__(256) k_gemm_fb(const float* __restrict__ bias,
                                                 float* __restrict__ out,
                                                 int M, int N, int K) {
#if !HAVE_TC
    __shared__ __align__(16) signed char As[2][128 * ASTRIDE];
    __shared__ __align__(16) signed char Bw[2][64 * ASTRIDE];
    __shared__ __align__(16) signed char Be[2][64 * ASTRIDE];

    int tid = threadIdx.x;
    int wid = tid >> 5, lane = tid & 31;
    int wm = wid >> 1, wn = wid & 1;
    int g = lane >> 2, tig = lane & 3;
    int row0 = blockIdx.y << 7, col0 = blockIdx.x << 6;

    int acc1[2][4][4], acc2[2][4][4];
    #pragma unroll
    for (int i = 0; i < 2; i++)
        #pragma unroll
        for (int j = 0; j < 4; j++)
            #pragma unroll
            for (int c = 0; c < 4; c++) { acc1[i][j][c] = 0; acc2[i][j][c] = 0; }

    int nkt = K >> 6;
    int a_r0 = tid >> 2, a_c = (tid & 3) * 16;
    int b_r  = tid >> 2, b_c = (tid & 3) * 16;

    {
        const signed char* gA = g_qx + (size_t)(row0 + a_r0) * K + a_c;
        cpa16g(&As[0][a_r0 * ASTRIDE + a_c], gA);
        cpa16g(&As[0][(a_r0 + 64) * ASTRIDE + a_c], gA + (size_t)64 * K);
        cpa16g(&Bw[0][b_r * ASTRIDE + b_c], g_qw + (size_t)(col0 + b_r) * K + b_c);
        cpa16g(&Be[0][b_r * ASTRIDE + b_c], g_qe + (size_t)(col0 + b_r) * K + b_c);
        asm volatile("cp.async.commit_group;\n");
    }

    #pragma unroll 1
    for (int kt = 0; kt < nkt; kt++) {
        asm volatile("cp.async.wait_group 0;\n");
        __syncthreads();

        if (kt + 1 < nkt) {
            int b = (kt + 1) & 1;
            int k0 = (kt + 1) << 6;
            const signed char* gA = g_qx + (size_t)(row0 + a_r0) * K + k0 + a_c;
            cpa16g(&As[b][a_r0 * ASTRIDE + a_c], gA);
            cpa16g(&As[b][(a_r0 + 64) * ASTRIDE + a_c], gA + (size_t)64 * K);
            cpa16g(&Bw[b][b_r * ASTRIDE + b_c], g_qw + (size_t)(col0 + b_r) * K + k0 + b_c);
            cpa16g(&Be[b][b_r * ASTRIDE + b_c], g_qe + (size_t)(col0 + b_r) * K + k0 + b_c);
            asm volatile("cp.async.commit_group;\n");
        }

        const signed char* Ab  = As[kt & 1];
        const signed char* Bwb = Bw[kt & 1];
        const signed char* Beb = Be[kt & 1];

        #pragma unroll
        for (int kseg = 0; kseg < 2; kseg++) {
            int koff = kseg * 32 + tig * 4;
            int a[2][4];
            #pragma unroll
            for (int mi = 0; mi < 2; mi++) {
                int r0 = wm * 32 + mi * 16 + g;
                a[mi][0] = *(const int*)&Ab[r0 * ASTRIDE + koff];
                a[mi][1] = *(const int*)&Ab[(r0 + 8) * ASTRIDE + koff];
                a[mi][2] = *(const int*)&Ab[r0 * ASTRIDE + koff + 16];
                a[mi][3] = *(const int*)&Ab[(r0 + 8) * ASTRIDE + koff + 16];
            }
            int bw[4][2], be2[4][2];
            #pragma unroll
            for (int ni = 0; ni < 4; ni++) {
                int rn = wn * 32 + ni * 8 + g;
                bw[ni][0]  = *(const int*)&Bwb[rn * ASTRIDE + koff];
                bw[ni][1]  = *(const int*)&Bwb[rn * ASTRIDE + koff + 16];
                be2[ni][0] = *(const int*)&Beb[rn * ASTRIDE + koff];
                be2[ni][1] = *(const int*)&Beb[rn * ASTRIDE + koff + 16];
            }
            #pragma unroll
            for (int mi = 0; mi < 2; mi++)
                #pragma unroll
                for (int ni = 0; ni < 4; ni++) {
                    mma_s8(acc1[mi][ni], a[mi], bw[ni]);
                    mma_s8(acc2[mi][ni], a[mi], be2[ni]);
                }
        }
        __syncthreads();
    }

    float sxw = g_xs * g_wsc;
    float ce  = g_xs * g_es;
    int xzpi = g_xzpi, wzpi = g_wzpi;
    long long kzz = (long long)K * xzpi * wzpi;
    float amin = __int_as_float(0x7f800000), amax = -amin;

    int   rsw_[4][2], rsqe_[4][2];
    float bias_[4][2];
    int cbase[4];
    #pragma unroll
    for (int ni = 0; ni < 4; ni++) {
        int c0 = col0 + wn * 32 + ni * 8 + tig * 2;
        cbase[ni] = c0;
        rsw_[ni][0] = g_rsw[c0];  rsw_[ni][1] = g_rsw[c0 + 1];
        rsqe_[ni][0] = g_rsqe[c0]; rsqe_[ni][1] = g_rsqe[c0 + 1];
        float2 bv = *(const float2*)(bias + c0);
        bias_[ni][0] = bv.x; bias_[ni][1] = bv.y;
    }

    #pragma unroll
    for (int mi = 0; mi < 2; mi++) {
        #pragma unroll
        for (int rr = 0; rr < 2; rr++) {
            int row = row0 + wm * 32 + mi * 16 + rr * 8 + g;
            long long rowc = (long long)wzpi * g_rsx[row] - kzz;
            #pragma unroll
            for (int ni = 0; ni < 4; ni++) {
                float ov[2];
                #pragma unroll
                for (int cc = 0; cc < 2; cc++) {
                    int v1 = acc1[mi][ni][rr * 2 + cc];
                    int v2 = acc2[mi][ni][rr * 2 + cc];
                    long long br = (long long)v1 - rowc - (long long)xzpi * rsw_[ni][cc];
                    float op = (float)br * sxw + bias_[ni][cc];
                    float act = op + ce * (float)((long long)v2 - (long long)xzpi * rsqe_[ni][cc]);
                    amin = fminf(amin, act);
                    amax = fmaxf(amax, act);
                    ov[cc] = op;
                }
                *(float2*)(out + (size_t)row * N + cbase[ni]) = make_float2(ov[0], ov[1]);
            }
        }
    }

    #pragma unroll
    for (int o = 16; o > 0; o >>= 1) {
        amin = fminf(amin, __shfl_xor_sync(0xffffffffu, amin, o));
        amax = fmaxf(amax, __shfl_xor_sync(0xffffffffu, amax, o));
    }
    __shared__ float smin[8], smax[8];
    if (lane == 0) { smin[wid] = amin; smax[wid] = amax; }
    __syncthreads();
    if (tid == 0) {
        #pragma unroll
        for (int i = 1; i < 8; i++) { amin = fminf(amin, smin[i]); amax = fmaxf(amax, smax[i]); }
        atomicMin(&g_keys[6], fkey(amin));
        atomicMax(&g_keys[7], fkey(amax));
    }
#endif  // !HAVE_TC
}

__global__ void k_scales2() {
    float amin = fdec(g_keys[6]), amax = fdec(g_keys[7]);
    float as = (amax - amin) / 255.0f;
    g_as = as;
    g_azp = rintf(0.0f - amin / as);
    g_ias = 1.0f / as;
}

__global__ void k_requant(float* __restrict__ out, long long n4) {
    float as = g_as, azp = g_azp, ias = g_ias;
    float4* p = (float4*)out;
    for (long long i = blockIdx.x * (long long)blockDim.x + threadIdx.x; i < n4;
         i += (long long)gridDim.x * blockDim.x) {
        float4 v = p[i];
        v.x = (fminf(255.f, fmaxf(0.f, rintf(fmaf(v.x, ias, azp)))) - azp) * as;
        v.y = (fminf(255.f, fmaxf(0.f, rintf(fmaf(v.y, ias, azp)))) - azp) * as;
        v.z = (fminf(255.f, fmaxf(0.f, rintf(fmaf(v.z, ias, azp)))) - azp) * as;
        v.w = (fminf(255.f, fmaxf(0.f, rintf(fmaf(v.w, ias, azp)))) - azp) * as;
        p[i] = v;
    }
}

// ---------------------------------------------------------------------------
// Host: tensor-map encoding via driver entry point (no -lcuda needed).
// ---------------------------------------------------------------------------
typedef CUresult (*encode_fn_t)(
    CUtensorMap*, CUtensorMapDataType, cuuint32_t, void*,
    const cuuint64_t*, const cuuint64_t*, const cuuint32_t*, const cuuint32_t*,
    CUtensorMapInterleave, CUtensorMapSwizzle, CUtensorMapL2promotion,
    CUtensorMapFloatOOBfill);

static void encode_bf16_2d(encode_fn_t fn, CUtensorMap* m, void* base,
                           unsigned long long rows, int K) {
    cuuint64_t dims[2]    = {(cuuint64_t)K, (cuuint64_t)rows};
    cuuint64_t strides[1] = {(cuuint64_t)K * 2};
    cuuint32_t box[2]     = {64u, 256u};
    cuuint32_t es[2]      = {1u, 1u};
    fn(m, CU_TENSOR_MAP_DATA_TYPE_BFLOAT16, 2, base, dims, strides, box, es,
       CU_TENSOR_MAP_INTERLEAVE_NONE, CU_TENSOR_MAP_SWIZZLE_128B,
       CU_TENSOR_MAP_L2_PROMOTION_L2_128B, CU_TENSOR_MAP_FLOAT_OOB_FILL_NONE);
}

extern "C" void kernel_launch(void* const* d_in, const int* in_sizes, int n_in,
                              void* d_out, int out_size) {
    const float* x = (const float*)d_in[0];
    const float* w = (const float*)d_in[1];
    const float* b = (const float*)d_in[2];
    float* out = (float*)d_out;

    int N = in_sizes[2];
    int K = in_sizes[1] / N;
    int M = in_sizes[0] / K;
    if (M > MAXM || N > MAXN || K > MAXK) return;
    if ((M & 255) || (N & 511) || (K & 127)) return;

    cudaFuncSetAttribute(k_gemm_tc, cudaFuncAttributeMaxDynamicSharedMemorySize, SMEM_TC);

    // Engine detection: inactive engine's kernel is an empty stub (few regs).
    int tc_live = 1, fb_live = 1;
    cudaFuncAttributes fa{};
    if (cudaFuncGetAttributes(&fa, (const void*)k_gemm_tc) == cudaSuccess) {
        if (fa.numRegs >= 40) fb_live = 0; else tc_live = 0;
    }

    encode_fn_t efn = nullptr;
    cudaDriverEntryPointQueryResult qres;
    cudaGetDriverEntryPoint("cuTensorMapEncodeTiled", (void**)&efn,
                            cudaEnableDefault, &qres);
    CUtensorMap tmA, tmB;
    void* pA = nullptr; void* pB = nullptr;
    cudaGetSymbolAddress(&pA, g_qxh);
    cudaGetSymbolAddress(&pB, g_qwh);
    if (efn && pA && pB) {
        encode_bf16_2d(efn, &tmA, pA, (unsigned long long)M, K);
        encode_bf16_2d(efn, &tmB, pB, (unsigned long long)N, K);
    } else if (tc_live) {
        return;
    }

    k_init<<<1, 32>>>();
    k_minmax2<<<864, 256>>>(x, (long long)M * K / 4, w, (long long)N * K / 4, 576);
    k_scales1<<<1, 1>>>();
    k_quant<<<M + N, 256>>>(x, w, M, K);

    if (tc_live) {
        dim3 grid_tc(N / 256, M / 256);
        k_gemm_tc<<<grid_tc, 256, SMEM_TC>>>(tmA, tmB, b, out, M, N, K);
        k_cand<<<1184, 256>>>(out, M, N, K);
    }
    if (fb_live) {
        dim3 grid_fb(N / 64, M / 128);
        k_gemm_fb<<<grid_fb, 256>>>(b, out, M, N, K);
    }
    k_scales2<<<1, 1>>>();
    k_requant<<<4096, 256>>>(out, (long long)M * N / 4);
}